// round 16
// baseline (speedup 1.0000x reference)
#include <cuda_runtime.h>
#include <cuda_fp16.h>
#include <cstdint>

#define NMAX 100000
#define EMAX 1600000
#define D 128

// ---- scratch (no allocations allowed -> __device__ globals) ----
__device__ int   g_deg[NMAX];                    // zero at load; re-zeroed by agg2 each call
__device__ float g_dinv[NMAX];
__device__ int   g_colptr[NMAX + 1];
__device__ int   g_cursor[NMAX];
__device__ int   g_srow[EMAX];
__device__ uint2 g_hbuf[(size_t)NMAX * D / 4];   // fp16 features (8B per lane-slot)
__device__ uint2 g_zbuf[(size_t)NMAX * D / 4];
__device__ int   g_part[256];

__device__ __forceinline__ float to_tf32(float x) {
    float y;
    asm("cvt.rna.tf32.f32 %0, %1;" : "=f"(y) : "f"(x));
    return y;
}

__device__ __forceinline__ float4 h4f(uint2 u) {
    __half2 a = *reinterpret_cast<__half2*>(&u.x);
    __half2 b = *reinterpret_cast<__half2*>(&u.y);
    float2 fa = __half22float2(a), fb = __half22float2(b);
    return make_float4(fa.x, fa.y, fb.x, fb.y);
}
__device__ __forceinline__ uint2 f4h(float a, float b, float c, float d) {
    uint2 u;
    *reinterpret_cast<__half2*>(&u.x) = __floats2half2_rn(a, b);
    *reinterpret_cast<__half2*>(&u.y) = __floats2half2_rn(c, d);
    return u;
}

// ---------------- degree count (g_deg pre-zeroed: load-time or by agg2) ----------------
__global__ void k_deg_count(const int* __restrict__ col, int e) {
    int i = blockIdx.x * blockDim.x + threadIdx.x;
    if (i < e) atomicAdd(&g_deg[col[i]], 1);
}

// ---------------- scan of g_deg -> g_colptr (+dinv fused) ----------------
#define SCAN_T 256
#define SCAN_I 8
#define SCAN_C (SCAN_T * SCAN_I)

__global__ void k_scan_partial(int n) {
    __shared__ int ss[SCAN_T];
    int b = blockIdx.x, tid = threadIdx.x;
    int base = b * SCAN_C + tid * SCAN_I;
    int s = 0;
    #pragma unroll
    for (int i = 0; i < SCAN_I; i++) {
        int idx = base + i;
        if (idx < n) s += g_deg[idx];
    }
    ss[tid] = s;
    __syncthreads();
    for (int off = SCAN_T / 2; off > 0; off >>= 1) {
        if (tid < off) ss[tid] += ss[tid + off];
        __syncthreads();
    }
    if (tid == 0) g_part[b] = ss[0];
}

// scan_final computes its own block offset from g_part
__global__ void k_scan_final(int n, int e) {
    __shared__ int ss[SCAN_T];
    __shared__ int s_off;
    int b = blockIdx.x, tid = threadIdx.x;

    ss[tid] = (tid < b) ? g_part[tid] : 0;
    __syncthreads();
    for (int off = SCAN_T / 2; off > 0; off >>= 1) {
        if (tid < off) ss[tid] += ss[tid + off];
        __syncthreads();
    }
    if (tid == 0) s_off = ss[0];
    __syncthreads();

    int base = b * SCAN_C + tid * SCAN_I;
    int vals[SCAN_I];
    int degs[SCAN_I];
    int local = 0;
    #pragma unroll
    for (int i = 0; i < SCAN_I; i++) {
        int idx = base + i;
        int v = (idx < n) ? g_deg[idx] : 0;
        degs[i] = v;
        vals[i] = local;
        local += v;
    }
    ss[tid] = local;
    __syncthreads();
    for (int off = 1; off < SCAN_T; off <<= 1) {
        int v = 0;
        if (tid >= off) v = ss[tid - off];
        __syncthreads();
        ss[tid] += v;
        __syncthreads();
    }
    int toff = s_off + ss[tid] - local;
    #pragma unroll
    for (int i = 0; i < SCAN_I; i++) {
        int idx = base + i;
        if (idx < n) {
            int p = toff + vals[i];
            g_colptr[idx] = p;
            g_cursor[idx] = p;
            g_dinv[idx] = rsqrtf((float)(degs[i] + 1));
        }
    }
    if (b == 0 && tid == 0) g_colptr[n] = e;
}

// ---------------- CSR fill (minimal: 4B srow) ----------------
__global__ void k_fill(const int* __restrict__ row, const int* __restrict__ col, int e) {
    int i = blockIdx.x * blockDim.x + threadIdx.x;
    if (i < e) {
        int p = atomicAdd(&g_cursor[col[i]], 1);
        g_srow[p] = row[i];
    }
}

// ---------------- in-place feature scale: hs = dinv (x) h ----------------
__global__ void k_scale(int n) {
    int idx = blockIdx.x * blockDim.x + threadIdx.x;   // uint2 slot
    if (idx >= n * 32) return;
    float dv = g_dinv[idx >> 5];
    float4 f = h4f(g_hbuf[idx]);
    g_hbuf[idx] = f4h(dv * f.x, dv * f.y, dv * f.z, dv * f.w);
}

// ---------------- tf32 mma.sync GEMM: C_fp16 = A @ W, optional row-scale epilogue ----------------
#define AST 68
#define BST 136
#define GSMEM_FLOATS (128 * AST + 64 * BST)   // 69632 B

#define MMA_TF32(d, a, b) \
    asm volatile("mma.sync.aligned.m16n8k8.row.col.f32.tf32.tf32.f32 " \
        "{%0,%1,%2,%3}, {%4,%5,%6,%7}, {%8,%9}, {%0,%1,%2,%3};" \
        : "+f"((d)[0]), "+f"((d)[1]), "+f"((d)[2]), "+f"((d)[3]) \
        : "r"((a)[0]), "r"((a)[1]), "r"((a)[2]), "r"((a)[3]), \
          "r"((b)[0]), "r"((b)[1]))

__device__ __forceinline__ float4 load4(const float* p) { return *(const float4*)p; }
__device__ __forceinline__ float4 load4(const __half* p) {
    return h4f(*(const uint2*)p);
}

template <typename AT>
__global__ void __launch_bounds__(256) k_gemm_mma(const AT* __restrict__ A,
                                                  const float* __restrict__ W,
                                                  __half* __restrict__ C, int n,
                                                  const float* __restrict__ dscale) {
    extern __shared__ float smem[];
    float* As = smem;
    float* Bs = smem + 128 * AST;

    int tid = threadIdx.x;
    int wid = tid >> 5, lane = tid & 31;
    int gq = lane >> 2;
    int cq = lane & 3;
    int row0 = blockIdx.x << 7;
    int wm = (wid >> 2) << 6;
    int wn = (wid & 3) << 5;

    float acc[4][4][4];
    #pragma unroll
    for (int mt = 0; mt < 4; mt++)
        #pragma unroll
        for (int nt = 0; nt < 4; nt++)
            #pragma unroll
            for (int i = 0; i < 4; i++)
                acc[mt][nt][i] = 0.f;

    const uint32_t* Au = (const uint32_t*)As;
    const uint32_t* Bu = (const uint32_t*)Bs;

    for (int ch = 0; ch < 2; ch++) {
        int k0 = ch << 6;
        #pragma unroll
        for (int it = 0; it < 8; it++) {
            int t = tid + it * 256;
            int m = t >> 4, kq = t & 15;
            int gm = row0 + m;
            float4 v = make_float4(0.f, 0.f, 0.f, 0.f);
            if (gm < n) v = load4(A + (size_t)gm * D + k0 + kq * 4);
            v.x = to_tf32(v.x); v.y = to_tf32(v.y);
            v.z = to_tf32(v.z); v.w = to_tf32(v.w);
            *(float4*)(As + m * AST + kq * 4) = v;
        }
        #pragma unroll
        for (int it = 0; it < 8; it++) {
            int t = tid + it * 256;
            int k = t >> 5, nq = t & 31;
            float4 v = *(const float4*)(W + (size_t)(k0 + k) * D + nq * 4);
            v.x = to_tf32(v.x); v.y = to_tf32(v.y);
            v.z = to_tf32(v.z); v.w = to_tf32(v.w);
            *(float4*)(Bs + k * BST + nq * 4) = v;
        }
        __syncthreads();

        #pragma unroll
        for (int kt = 0; kt < 8; kt++) {
            int kl = kt << 3;
            uint32_t a[4][4];
            uint32_t b[4][2];
            #pragma unroll
            for (int mt = 0; mt < 4; mt++) {
                const uint32_t* ap = Au + (wm + (mt << 4)) * AST + kl;
                a[mt][0] = ap[gq * AST + cq];
                a[mt][1] = ap[(gq + 8) * AST + cq];
                a[mt][2] = ap[gq * AST + cq + 4];
                a[mt][3] = ap[(gq + 8) * AST + cq + 4];
            }
            #pragma unroll
            for (int nt = 0; nt < 4; nt++) {
                const uint32_t* bp = Bu + kl * BST + wn + (nt << 3);
                b[nt][0] = bp[cq * BST + gq];
                b[nt][1] = bp[(cq + 4) * BST + gq];
            }
            #pragma unroll
            for (int mt = 0; mt < 4; mt++)
                #pragma unroll
                for (int nt = 0; nt < 4; nt++)
                    MMA_TF32(acc[mt][nt], a[mt], b[nt]);
        }
        __syncthreads();
    }

    #pragma unroll
    for (int mt = 0; mt < 4; mt++) {
        int r0 = row0 + wm + (mt << 4) + gq;
        int r1 = r0 + 8;
        float s0 = 1.f, s1 = 1.f;
        if (dscale) {
            if (r0 < n) s0 = dscale[r0];
            if (r1 < n) s1 = dscale[r1];
        }
        #pragma unroll
        for (int nt = 0; nt < 4; nt++) {
            int cc = wn + (nt << 3) + (cq << 1);
            if (r0 < n)
                *(__half2*)(C + (size_t)r0 * D + cc) =
                    __floats2half2_rn(s0 * acc[mt][nt][0], s0 * acc[mt][nt][1]);
            if (r1 < n)
                *(__half2*)(C + (size_t)r1 * D + cc) =
                    __floats2half2_rn(s1 * acc[mt][nt][2], s1 * acc[mt][nt][3]);
        }
    }
}

// ---------------- aggregation (weightless gather of pre-scaled fp16 rows) ----------------
// out[c] = dc*(sum_r hs[r] + hs[c]) + b ; one warp per node, 2-deep pipeline.
__device__ __forceinline__ void store4(float* p, float a, float b, float c, float d) {
    *(float4*)p = make_float4(a, b, c, d);
}
__device__ __forceinline__ void store4(__half* p, float a, float b, float c, float d) {
    *(uint2*)p = f4h(a, b, c, d);
}

template <typename OT>
__global__ void k_agg(const __half* __restrict__ hs, const float* __restrict__ bias,
                      OT* __restrict__ out, int n, int do_relu, int zero_deg) {
    int gt = blockIdx.x * blockDim.x + threadIdx.x;
    int c = gt >> 5;
    int lane = gt & 31;
    if (c >= n) return;

    float dc = g_dinv[c];
    const uint2* h4p = (const uint2*)hs;
    float4 sv = h4f(h4p[(size_t)c * 32 + lane]);   // hs[c] (already dinv-scaled)

    float ax = sv.x, ay = sv.y, az = sv.z, aw = sv.w;
    const uint2 ZU = make_uint2(0u, 0u);

    int i = g_colptr[c];
    int end = g_colptr[c + 1];
    uint2 u0 = ZU, u1 = ZU;
    if (i < end)     u0 = h4p[(size_t)g_srow[i] * 32 + lane];
    if (i + 1 < end) u1 = h4p[(size_t)g_srow[i + 1] * 32 + lane];
    for (; i < end; i++) {
        uint2 u2 = ZU;
        if (i + 2 < end) u2 = h4p[(size_t)g_srow[i + 2] * 32 + lane];
        float4 f = h4f(u0);
        ax += f.x; ay += f.y; az += f.z; aw += f.w;
        u0 = u1; u1 = u2;
    }

    float4 bv = ((const float4*)bias)[lane];
    ax = dc * ax + bv.x;
    ay = dc * ay + bv.y;
    az = dc * az + bv.z;
    aw = dc * aw + bv.w;
    if (do_relu) {
        ax = fmaxf(ax, 0.f); ay = fmaxf(ay, 0.f);
        az = fmaxf(az, 0.f); aw = fmaxf(aw, 0.f);
    }
    store4(out + (size_t)c * D + lane * 4, ax, ay, az, aw);

    // restore g_deg = 0 for the next call (replaces k_deg_init launch)
    if (zero_deg && lane == 0) g_deg[c] = 0;
}

// ---------------- launch ----------------
extern "C" void kernel_launch(void* const* d_in, const int* in_sizes, int n_in,
                              void* d_out, int out_size) {
    const float* x  = (const float*)d_in[0];
    const int*   ei = (const int*)d_in[1];
    const float* W1 = (const float*)d_in[2];
    const float* b1 = (const float*)d_in[3];
    const float* W2 = (const float*)d_in[4];
    const float* b2 = (const float*)d_in[5];
    float* out = (float*)d_out;

    int n = in_sizes[0] / D;
    int e = in_sizes[1] / 2;
    const int* row = ei;
    const int* col = ei + e;

    void *ph = nullptr, *pz = nullptr, *pd = nullptr;
    cudaGetSymbolAddress(&ph, g_hbuf);
    cudaGetSymbolAddress(&pz, g_zbuf);
    cudaGetSymbolAddress(&pd, g_dinv);
    __half* h = (__half*)ph;
    __half* z = (__half*)pz;
    const float* dinv = (const float*)pd;

    static int init_done = 0;
    static cudaStream_t s2 = nullptr;
    static cudaEvent_t ev_fork = nullptr, ev_scan = nullptr, ev_join = nullptr;
    if (!init_done) {
        cudaFuncSetAttribute(k_gemm_mma<float>, cudaFuncAttributeMaxDynamicSharedMemorySize,
                             GSMEM_FLOATS * 4);
        cudaFuncSetAttribute(k_gemm_mma<__half>, cudaFuncAttributeMaxDynamicSharedMemorySize,
                             GSMEM_FLOATS * 4);
        if (cudaStreamCreateWithFlags(&s2, cudaStreamNonBlocking) != cudaSuccess) s2 = nullptr;
        if (cudaEventCreateWithFlags(&ev_fork, cudaEventDisableTiming) != cudaSuccess) ev_fork = nullptr;
        if (cudaEventCreateWithFlags(&ev_scan, cudaEventDisableTiming) != cudaSuccess) ev_scan = nullptr;
        if (cudaEventCreateWithFlags(&ev_join, cudaEventDisableTiming) != cudaSuccess) ev_join = nullptr;
        init_done = 1;
    }
    bool fork = (s2 && ev_fork && ev_scan && ev_join);
    cudaStream_t sc = fork ? s2 : (cudaStream_t)0;

    int nb = (n + SCAN_C - 1) / SCAN_C;
    int gemm_blocks = (n + 127) / 128;
    int agg_blocks = (n * 32 + 255) / 256;
    int scale_blocks = (n * 32 + 255) / 256;

    if (fork) {
        cudaEventRecord(ev_fork, 0);
        cudaStreamWaitEvent(s2, ev_fork, 0);
    }

    // ---- CSR build chain (side stream when forked); g_deg already zeroed ----
    k_deg_count<<<(e + 255) / 256, 256, 0, sc>>>(col, e);
    k_scan_partial<<<nb, SCAN_T, 0, sc>>>(n);
    k_scan_final<<<nb, SCAN_T, 0, sc>>>(n, e);
    if (fork) cudaEventRecord(ev_scan, s2);        // dinv ready
    k_fill<<<(e + 255) / 256, 256, 0, sc>>>(row, col, e);
    if (fork) cudaEventRecord(ev_join, s2);

    // ---- GEMM1 (fp32 in, fp16 out, no scale) overlaps the CSR build ----
    k_gemm_mma<float><<<gemm_blocks, 256, GSMEM_FLOATS * 4>>>(x, W1, h, n, nullptr);

    // hs = dinv (x) h  — needs dinv (ev_scan) but NOT the fill; overlaps k_fill
    if (fork) cudaStreamWaitEvent((cudaStream_t)0, ev_scan, 0);
    k_scale<<<scale_blocks, 256>>>(n);

    if (fork) cudaStreamWaitEvent((cudaStream_t)0, ev_join, 0);

    // layer 1 aggregate: z = relu(dc*(sum hs) + b1)   (fp16 out)
    k_agg<__half><<<agg_blocks, 256>>>(h, b1, z, n, 1, 0);
    // layer 2: hs2 = dinv (x) (z @ W2) via epilogue ; out = dc*(sum hs2) + b2
    k_gemm_mma<__half><<<gemm_blocks, 256, GSMEM_FLOATS * 4>>>(z, W2, h, n, dinv);
    k_agg<float><<<agg_blocks, 256>>>(h, b2, out, n, 0, 1);
}